// round 17
// baseline (speedup 1.0000x reference)
#include <cuda_runtime.h>
#include <cuda_fp16.h>
#include <cstdint>

// out[b,i,j,m] = tanh( sum_d v1[b,i,d] * kernel[m,d] * v2[b,j,d] )
#define PB   64
#define PT1  128
#define PT2  160
#define PD   768
#define PM   64

#define NS16     48                   // 16-wide k-slices total
#define KSC      4                    // slices per chunk (K=64)
#define NCHUNK   (NS16 / KSC)         // 12
#define NT       320                  // 10 warps
#define I_PER    2
#define NITEMS   (PB * (PT1 / I_PER) * 2)   // 8192 = b * i-group * j-half

#define PRSTR    320                  // v2 pair-row stride (conflict-free LDS.128)
#define STGV2    (40 * PRSTR)         // 12800 (one j-half)
#define SLICE_B  2176                 // kern bytes per k16 slice
#define STGKP    (KSC * SLICE_B)      // 8704
#define STGB     (STGV2 + STGKP)      // 21504
#define V1TD     6144                 // two v1 tables (double-buffered), 3072 each
#define SMEM_TOTAL (V1TD + 3 * STGB)  // 70656  (x3 CTAs = 211968 <= 228KB)

#define V2HN (PB * 80 * NS16 * 4)     // 983040 float4 entries
#define KHN  (NS16 * 4 * PM)          // 12288 float2 slots

// ---- device-global fp16-prepped operands (layouts unchanged) ----
__device__ __align__(16) float4 g_v2h[V2HN];
__device__ __align__(16) float2 g_kh[NS16 * 272];

__device__ __forceinline__ float tanh_mufu(float x) {
    float r;
    asm("tanh.approx.f32 %0, %1;" : "=f"(r) : "f"(x));
    return r;
}
__device__ __forceinline__ uint32_t s2u(const void* p) {
    uint32_t a;
    asm("{ .reg .u64 t; cvta.to.shared.u64 t, %1; cvt.u32.u64 %0, t; }" : "=r"(a) : "l"(p));
    return a;
}
__device__ __forceinline__ void cpa16(uint32_t dst, const void* src) {
    asm volatile("cp.async.cg.shared.global [%0], [%1], 16;" :: "r"(dst), "l"(src));
}
__device__ __forceinline__ uint32_t h2pack(float x, float y) {
    __half2 h = __floats2half2_rn(x, y);
    return *(uint32_t*)&h;
}
__device__ __forceinline__ uint32_t hmul2(uint32_t a, uint32_t b) {
    uint32_t d;
    asm("mul.rn.f16x2 %0, %1, %2;" : "=r"(d) : "r"(a), "r"(b));
    return d;
}

// ---- prep: fp16-convert + permute v2 and kernel (unchanged) ----
__global__ void prep_all(const float* __restrict__ v2, const float* __restrict__ kern) {
    int t = blockIdx.x * blockDim.x + threadIdx.x;
    if (t < V2HN) {
        int qc = t & 3;
        int t2 = t >> 2;
        int s  = t2 % NS16;
        int pr = (t2 / NS16) % 80;
        int b  = t2 / (NS16 * 80);
        int j  = (pr >> 3) * 16 + (pr & 7);
        int d0 = s * 16 + 2 * qc;
        const float* p0 = v2 + ((size_t)(b * PT2 + j) * PD + d0);
        const float* p8 = p0 + 8 * PD;
        float4 o;
        o.x = __uint_as_float(h2pack(p0[0], p0[1]));
        o.y = __uint_as_float(h2pack(p8[0], p8[1]));
        o.z = __uint_as_float(h2pack(p0[8], p0[9]));
        o.w = __uint_as_float(h2pack(p8[8], p8[9]));
        g_v2h[t] = o;
    } else if (t < V2HN + KHN) {
        int u  = t - V2HN;
        int m  = u & 63;
        int qc = (u >> 6) & 3;
        int s  = u >> 8;
        int d0 = s * 16 + 2 * qc;
        const float* kp = kern + (size_t)m * PD + d0;
        float2 o;
        o.x = __uint_as_float(h2pack(kp[0], kp[1]));
        o.y = __uint_as_float(h2pack(kp[8], kp[9]));
        g_kh[s * 272 + qc * 68 + m] = o;
    }
}

extern __shared__ char dynsmem[];

// stage one chunk: v2 j-half (640 f4) + kern (544 x 16B)
__device__ __forceinline__ void prefetch_stage(uint32_t stg, int b, int h, int s0, int tid) {
#pragma unroll
    for (int it = 0; it < 2; it++) {
        int t = tid + it * NT;
        int p = t >> 4, r = t & 15;
        cpa16(stg + p * PRSTR + r * 16,
              g_v2h + (((size_t)b * 80 + 40 * h + p) * NS16 + s0 + (r >> 2)) * 4 + (r & 3));
    }
#pragma unroll
    for (int it = 0; it < 2; it++) {
        int t = tid + it * NT;
        if (t < STGKP / 16)
            cpa16(stg + STGV2 + t * 16, (const char*)g_kh + (size_t)s0 * SLICE_B + t * 16);
    }
}

// build v1 fp16 pair table (LDG + STS) into table buffer `tb` (0/1)
__device__ __forceinline__ void build_v1(const float* v1b, int tb, int tid) {
    for (int t = tid; t < I_PER * 192; t += NT) {
        int iv = (t >= 192) ? 1 : 0;
        int r  = t - iv * 192;
        int s  = r >> 2, q = r & 3;
        int d0 = s * 16 + 2 * q;
        const float* vp = v1b + (size_t)iv * PD + d0;
        float2 o;
        o.x = __uint_as_float(h2pack(vp[0], vp[1]));
        o.y = __uint_as_float(h2pack(vp[8], vp[9]));
        *(float2*)(dynsmem + (size_t)(tb * 384 + t) * 8) = o;
    }
}

__global__ __launch_bounds__(NT, 3)
void mpcos_main(const float* __restrict__ v1, float* __restrict__ out)
{
    const uint32_t sb = s2u(dynsmem);
    const int tid  = threadIdx.x;
    const int w    = tid >> 5, lane = tid & 31;
    const int qrow = lane >> 2, qc = lane & 3;
    const int mw   = w / 5, t5 = w % 5;
    const int step = gridDim.x;

    int item = blockIdx.x;
    if (item >= NITEMS) return;

    // ---- prologue for first item ----
    {
        int b_  = item >> 7;
        int i0_ = ((item & 127) >> 1) * I_PER;
        int h_  = item & 1;
        build_v1(v1 + ((size_t)b_ * PT1 + i0_) * PD, 0, tid);
        prefetch_stage(sb + V1TD + 0 * STGB, b_, h_, 0, tid);
        asm volatile("cp.async.commit_group;" ::: "memory");
        prefetch_stage(sb + V1TD + 1 * STGB, b_, h_, KSC, tid);
        asm volatile("cp.async.commit_group;" ::: "memory");
    }

    // prefetch cursor: next global chunk to fetch is chunk 2 of `item`
    int pf_item = item, pf_c = 2, pf_s = 2;
    int pf_b = item >> 7, pf_h = item & 1;
    int pf_valid = 1;
    int tbl = 0;
    int scc = 0;                                   // current stage (cc % 3)

    const uint32_t aoff_rel = (uint32_t)((t5 * 8 + qrow) * PRSTR + qc * 16);
    const uint32_t boff_rel = (uint32_t)(STGV2 + qc * 544 + (mw * 32 + qrow) * 8);

    while (true) {
        const int b  = item >> 7;
        const int i0 = ((item & 127) >> 1) * I_PER;
        const int h  = item & 1;
        const int nxt = item + step;
        const int nxt_valid = (nxt < NITEMS);

        float acc[I_PER][4][4] = {};

        for (int c = 0; c < NCHUNK; c++) {
            asm volatile("cp.async.wait_group 1;" ::: "memory");
            __syncthreads();

            // issue prefetch for global chunk +2 (always commit to keep groups uniform)
            if (pf_valid)
                prefetch_stage(sb + V1TD + pf_s * STGB, pf_b, pf_h, pf_c * KSC, tid);
            asm volatile("cp.async.commit_group;" ::: "memory");
            pf_s = (pf_s == 2) ? 0 : pf_s + 1;
            if (++pf_c == NCHUNK) {
                pf_c = 0;
                pf_item += step;
                if (pf_item >= NITEMS) pf_valid = 0;
                else { pf_b = pf_item >> 7; pf_h = pf_item & 1; }
            }

            // last chunk: rebuild v1 table for next item into the other buffer
            // (LDG latency hidden under this chunk's MMAs; first read is after
            //  the next item's chunk-0 __syncthreads)
            if (c == NCHUNK - 1 && nxt_valid) {
                int nb  = nxt >> 7;
                int ni0 = ((nxt & 127) >> 1) * I_PER;
                build_v1(v1 + ((size_t)nb * PT1 + ni0) * PD, tbl ^ 1, tid);
            }

            const char* stg = dynsmem + V1TD + scc * STGB;
            scc = (scc == 2) ? 0 : scc + 1;
            const int vslot = tbl * 384 + c * 16 + qc;

#pragma unroll
            for (int ks = 0; ks < KSC; ks++) {
                const float4 va = *(const float4*)(stg + aoff_rel + ks * 64);
                const float2 p0 = *(const float2*)(dynsmem + (size_t)(vslot + ks * 4) * 8);
                const float2 p1 = *(const float2*)(dynsmem + (size_t)(192 + vslot + ks * 4) * 8);

                uint32_t A0[4], A1[4];
                A0[0] = hmul2(__float_as_uint(va.x), __float_as_uint(p0.x));
                A0[1] = hmul2(__float_as_uint(va.y), __float_as_uint(p0.x));
                A0[2] = hmul2(__float_as_uint(va.z), __float_as_uint(p0.y));
                A0[3] = hmul2(__float_as_uint(va.w), __float_as_uint(p0.y));
                A1[0] = hmul2(__float_as_uint(va.x), __float_as_uint(p1.x));
                A1[1] = hmul2(__float_as_uint(va.y), __float_as_uint(p1.x));
                A1[2] = hmul2(__float_as_uint(va.z), __float_as_uint(p1.y));
                A1[3] = hmul2(__float_as_uint(va.w), __float_as_uint(p1.y));

                const char* bb = stg + boff_rel + ks * SLICE_B;
#pragma unroll
                for (int nt = 0; nt < 4; nt++) {
                    const uint2 bf = *(const uint2*)(bb + nt * 64);
#define DO_MMA(ACC, AR)                                                         \
                    asm volatile(                                               \
                        "mma.sync.aligned.m16n8k16.row.col.f32.f16.f16.f32 "   \
                        "{%0,%1,%2,%3}, {%4,%5,%6,%7}, {%8,%9}, {%0,%1,%2,%3};"\
                        : "+f"(ACC[0]), "+f"(ACC[1]), "+f"(ACC[2]), "+f"(ACC[3])\
                        : "r"(AR[0]), "r"(AR[1]), "r"(AR[2]), "r"(AR[3]),      \
                          "r"(bf.x), "r"(bf.y))
                    DO_MMA(acc[0][nt], A0);
                    DO_MMA(acc[1][nt], A1);
#undef DO_MMA
                }
            }
        }

        // ---- epilogue: MUFU.TANH + store ----
        const int jr = (5 * h + t5) * 16 + qrow;
#pragma unroll
        for (int ii = 0; ii < I_PER; ii++) {
            float* ob = out + ((size_t)(b * PT1 + i0 + ii) * PT2) * PM;
#pragma unroll
            for (int nt = 0; nt < 4; nt++) {
                const int col = mw * 32 + nt * 8 + 2 * qc;
                float2 r0, r1;
                r0.x = tanh_mufu(acc[ii][nt][0]);
                r0.y = tanh_mufu(acc[ii][nt][1]);
                r1.x = tanh_mufu(acc[ii][nt][2]);
                r1.y = tanh_mufu(acc[ii][nt][3]);
                *(float2*)(ob + (size_t)jr * PM + col)       = r0;
                *(float2*)(ob + (size_t)(jr + 8) * PM + col) = r1;
            }
        }

        if (!nxt_valid) break;
        tbl ^= 1;
        item = nxt;
    }
}

extern "C" void kernel_launch(void* const* d_in, const int* in_sizes, int n_in,
                              void* d_out, int out_size)
{
    const float* v1 = nullptr;
    const float* v2 = nullptr;
    const float* kern = nullptr;
    for (int idx = 0; idx < n_in; idx++) {
        if (in_sizes[idx] == PB * PT1 * PD)      v1   = (const float*)d_in[idx];
        else if (in_sizes[idx] == PB * PT2 * PD) v2   = (const float*)d_in[idx];
        else if (in_sizes[idx] == PM * PD)       kern = (const float*)d_in[idx];
    }
    float* out = (float*)d_out;

    prep_all<<<(V2HN + KHN + 255) / 256, 256>>>(v2, kern);

    int smc = 148;
    cudaDeviceGetAttribute(&smc, cudaDevAttrMultiProcessorCount, 0);
    int grid = smc * 3;                 // exactly one persistent wave (3 CTAs/SM)
    if (grid > NITEMS) grid = NITEMS;

    cudaFuncSetAttribute(mpcos_main, cudaFuncAttributeMaxDynamicSharedMemorySize, SMEM_TOTAL);
    mpcos_main<<<grid, NT, SMEM_TOTAL>>>(v1, out);
}